// round 6
// baseline (speedup 1.0000x reference)
#include <cuda_runtime.h>
#include <cuda_bf16.h>
#include <cstdint>

#define RB     64
#define RT     512
#define RACT   1024
#define RM     (RT * RB)        // 32768
#define CHUNK  16
#define NCHUNK (RT / CHUNK)     // 32
#define MP     (NCHUNK * RB)    // 2048

// ---------------- scratch (device globals: allocation-free) ----------------
__device__ __align__(256) float g_U[RM * RACT];
__device__ __align__(256) float g_V[MP * RACT];          // v_c fp32 (pass-1 finals)
__device__ __align__(256) float g_F[RACT * RACT];
__device__ __align__(256) float g_F2[RACT * RACT];

__device__ __align__(256) __nv_bfloat16 g_Xhi[RM * RACT],  g_Xlo[RM * RACT];
__device__ __align__(256) __nv_bfloat16 g_Ahi[RM * RACT],  g_Alo[RM * RACT];
__device__ __align__(256) __nv_bfloat16 g_W1hi[RACT * RACT], g_W1lo[RACT * RACT]; // Wax
__device__ __align__(256) __nv_bfloat16 g_W2hi[RACT * RACT], g_W2lo[RACT * RACT]; // Wy
__device__ __align__(256) __nv_bfloat16 g_W3hi[RACT * RACT], g_W3lo[RACT * RACT]; // Waa
__device__ __align__(256) __nv_bfloat16 g_Mhi[RACT * RACT],  g_Mlo[RACT * RACT];  // (W^T)^(2^k)
__device__ __align__(256) __nv_bfloat16 g_Nhi[RACT * RACT],  g_Nlo[RACT * RACT];  // W^(2^k)
__device__ __align__(256) __nv_bfloat16 g_Bndhi[(NCHUNK + 1) * RB * RACT];
__device__ __align__(256) __nv_bfloat16 g_Bndlo[(NCHUNK + 1) * RB * RACT];

// ---------------- PTX helpers ----------------
__device__ __forceinline__ uint32_t s2u(const void* p) {
    uint32_t a;
    asm("{ .reg .u64 t; cvta.to.shared.u64 t, %1; cvt.u32.u64 %0, t; }" : "=r"(a) : "l"(p));
    return a;
}
__device__ __forceinline__ void cpa16(uint32_t d, const void* s) {
    asm volatile("cp.async.cg.shared.global [%0], [%1], 16;\n" :: "r"(d), "l"(s));
}
__device__ __forceinline__ void cp_commit() { asm volatile("cp.async.commit_group;\n" ::: "memory"); }
template <int N> __device__ __forceinline__ void cp_wait() {
    asm volatile("cp.async.wait_group %0;\n" :: "n"(N) : "memory");
}
__device__ __forceinline__ void ldsm4(uint32_t& r0, uint32_t& r1, uint32_t& r2, uint32_t& r3,
                                      uint32_t addr) {
    asm volatile("ldmatrix.sync.aligned.m8n8.x4.shared.b16 {%0,%1,%2,%3}, [%4];"
                 : "=r"(r0), "=r"(r1), "=r"(r2), "=r"(r3) : "r"(addr));
}
__device__ __forceinline__ void mma16816(float* c, const uint32_t* a, const uint32_t* b) {
    asm volatile(
        "mma.sync.aligned.m16n8k16.row.col.f32.bf16.bf16.f32 "
        "{%0,%1,%2,%3}, {%4,%5,%6,%7}, {%8,%9}, {%0,%1,%2,%3};"
        : "+f"(c[0]), "+f"(c[1]), "+f"(c[2]), "+f"(c[3])
        : "r"(a[0]), "r"(a[1]), "r"(a[2]), "r"(a[3]), "r"(b[0]), "r"(b[1]));
}

// ---------------- split helpers ----------------
__device__ __forceinline__ unsigned short f2bh(float x) {
    return __bfloat16_as_ushort(__float2bfloat16(x));
}
__device__ __forceinline__ unsigned short f2bl(float x, unsigned short h) {
    return __bfloat16_as_ushort(__float2bfloat16(x - __bfloat162float(__ushort_as_bfloat16(h))));
}

__global__ void split_rt(const float4* __restrict__ src,
                         ushort4* __restrict__ hi, ushort4* __restrict__ lo, int n4) {
    int i = blockIdx.x * blockDim.x + threadIdx.x;
    if (i >= n4) return;
    float4 v = src[i];
    ushort4 h, l;
    h.x = f2bh(v.x); l.x = f2bl(v.x, h.x);
    h.y = f2bh(v.y); l.y = f2bl(v.y, h.y);
    h.z = f2bh(v.z); l.z = f2bl(v.z, h.z);
    h.w = f2bh(v.w); l.w = f2bl(v.w, h.w);
    hi[i] = h; lo[i] = l;
}

// transpose-split: out[j][i] = split(src[i][j]); coalesced writes
__global__ void tns(const float* __restrict__ src,
                    __nv_bfloat16* __restrict__ hi, __nv_bfloat16* __restrict__ lo) {
    int idx = blockIdx.x * blockDim.x + threadIdx.x;
    int j = idx >> 10, i = idx & 1023;
    float v = src[(size_t)i * 1024 + j];
    unsigned short h = f2bh(v), l = f2bl(v, h);
    hi[idx] = __ushort_as_bfloat16(h);
    lo[idx] = __ushort_as_bfloat16(l);
}

// pass-1 init: g_A rows c*1024+b <- split(g_U rows (c*16)*64+b = c*1024+b)
__global__ void split_gatherA() {
    int i = blockIdx.x * blockDim.x + threadIdx.x;      // MP*256 float4s
    int row = i >> 8;                                   // c*64 + b
    int c4  = (i & 255) * 4;
    size_t off = ((size_t)((row >> 6) * 1024 + (row & 63))) * 1024 + c4;
    float4 v = *reinterpret_cast<const float4*>(g_U + off);
    ushort4 h, l;
    h.x = f2bh(v.x); l.x = f2bl(v.x, h.x);
    h.y = f2bh(v.y); l.y = f2bl(v.y, h.y);
    h.z = f2bh(v.z); l.z = f2bl(v.z, h.z);
    h.w = f2bh(v.w); l.w = f2bl(v.w, h.w);
    *reinterpret_cast<ushort4*>(g_Ahi + off) = h;
    *reinterpret_cast<ushort4*>(g_Alo + off) = l;
}

__global__ void zero_bnd() {
    int i = blockIdx.x * blockDim.x + threadIdx.x;      // 16384 ushort4s = rows 0..63
    ushort4 z = {0, 0, 0, 0};
    reinterpret_cast<ushort4*>(g_Bndhi)[i] = z;
    reinterpret_cast<ushort4*>(g_Bndlo)[i] = z;
}

// ---------------- unified HMMA GEMM (bf16x3 split) ----------------
// C[m][n] = sum_k A[m][k]*B[n][k] (+ bias[n] if non-null) (+ Uf[urow][n] if non-null)
// row remaps: row' = (m>>6)*r0 + (m&63)*r1 + r2
// EPI 0: fp32 store to Cf.   EPI 1: bf16 hi/lo split store to Chi/Clo.
#define TILE_B  10240
#define STG_B   (4 * TILE_B)
#define GSMEM   (3 * STG_B)

template <int EPI>
__global__ void __launch_bounds__(256, 1) gmma(
    const __nv_bfloat16* __restrict__ Ah, const __nv_bfloat16* __restrict__ Al,
    const __nv_bfloat16* __restrict__ Bh, const __nv_bfloat16* __restrict__ Bl,
    const float* __restrict__ bias, float* __restrict__ Cf,
    __nv_bfloat16* __restrict__ Chi, __nv_bfloat16* __restrict__ Clo,
    const float* __restrict__ Uf,
    int a0, int a1, int a2, int c0, int c1, int c2, int u0, int u1, int u2)
{
    extern __shared__ char smc[];
    const uint32_t sbase = s2u(smc);

    const int tid  = threadIdx.x;
    const int wid  = tid >> 5, lane = tid & 31;
    const int n0   = blockIdx.x * 128, m0 = blockIdx.y * 128;
    const int wM   = (wid & 1) * 64;
    const int wN   = (wid >> 1) * 32;

    const char* srcp[8];
    uint32_t dsto[8];
#pragma unroll
    for (int i = 0; i < 8; i++) {
        int idx = i * 256 + tid;
        int buf = idx >> 9;
        int r   = (idx >> 2) & 127;
        int s   = idx & 3;
        dsto[i] = (uint32_t)(buf * TILE_B + r * 80 + s * 16);
        size_t grow;
        const __nv_bfloat16* p;
        if (buf < 2) {
            int row = m0 + r;
            grow = (size_t)((row >> 6) * a0 + (row & 63) * a1 + a2);
            p = (buf == 0) ? Ah : Al;
        } else {
            grow = (size_t)(n0 + r);
            p = (buf == 2) ? Bh : Bl;
        }
        srcp[i] = (const char*)p + grow * 2048 + s * 16;
    }

#pragma unroll
    for (int st = 0; st < 2; st++) {
#pragma unroll
        for (int i = 0; i < 8; i++)
            cpa16(sbase + st * STG_B + dsto[i], srcp[i] + st * 64);
        cp_commit();
    }

    float acc[4][4][4];
#pragma unroll
    for (int a = 0; a < 4; a++)
#pragma unroll
        for (int b = 0; b < 4; b++)
#pragma unroll
            for (int c = 0; c < 4; c++) acc[a][b][c] = 0.f;

    const int j   = lane >> 3;
    const int arl = (lane & 7) + (j & 1) * 8;
    const int brl = (lane & 7) + (j >> 1) * 8;

    for (int c = 0; c < 32; c++) {
        cp_wait<1>();
        __syncthreads();
        if (c + 2 < 32) {
            uint32_t sb2 = sbase + ((c + 2) % 3) * STG_B;
#pragma unroll
            for (int i = 0; i < 8; i++)
                cpa16(sb2 + dsto[i], srcp[i] + (c + 2) * 64);
        }
        cp_commit();

        const uint32_t sb = sbase + (c % 3) * STG_B;
#pragma unroll
        for (int kt = 0; kt < 2; kt++) {
            const int aseg = kt * 2 + (j >> 1);
            const int bseg = kt * 2 + (j & 1);
            uint32_t ah[4][4], al[4][4];
#pragma unroll
            for (int mt = 0; mt < 4; mt++) {
                uint32_t ra = sb + (uint32_t)((wM + mt * 16 + arl) * 80 + aseg * 16);
                ldsm4(ah[mt][0], ah[mt][1], ah[mt][2], ah[mt][3], ra);
                ldsm4(al[mt][0], al[mt][1], al[mt][2], al[mt][3], ra + TILE_B);
            }
            uint32_t bh[4][2], bl[4][2];
#pragma unroll
            for (int bt = 0; bt < 2; bt++) {
                uint32_t rb = sb + 2 * TILE_B + (uint32_t)((wN + bt * 16 + brl) * 80 + bseg * 16);
                uint32_t t0, t1, t2, t3;
                ldsm4(t0, t1, t2, t3, rb);
                bh[bt * 2][0] = t0; bh[bt * 2][1] = t1;
                bh[bt * 2 + 1][0] = t2; bh[bt * 2 + 1][1] = t3;
                ldsm4(t0, t1, t2, t3, rb + TILE_B);
                bl[bt * 2][0] = t0; bl[bt * 2][1] = t1;
                bl[bt * 2 + 1][0] = t2; bl[bt * 2 + 1][1] = t3;
            }
#pragma unroll
            for (int mt = 0; mt < 4; mt++)
#pragma unroll
                for (int nt = 0; nt < 4; nt++) {
                    mma16816(acc[mt][nt], ah[mt], bh[nt]);
                    mma16816(acc[mt][nt], ah[mt], bl[nt]);
                    mma16816(acc[mt][nt], al[mt], bh[nt]);
                }
        }
    }

    if (EPI == 0) {
        float2 bb[4];
#pragma unroll
        for (int nt = 0; nt < 4; nt++) {
            int col = n0 + wN + nt * 8 + (lane & 3) * 2;
            if (bias) { bb[nt].x = bias[col]; bb[nt].y = bias[col + 1]; }
            else      { bb[nt].x = 0.f;       bb[nt].y = 0.f; }
        }
#pragma unroll
        for (int mt = 0; mt < 4; mt++)
#pragma unroll
            for (int h = 0; h < 2; h++) {
                int row = m0 + wM + mt * 16 + (lane >> 2) + h * 8;
                size_t crow = (size_t)((row >> 6) * c0 + (row & 63) * c1 + c2);
                size_t urow = (size_t)((row >> 6) * u0 + (row & 63) * u1 + u2);
#pragma unroll
                for (int nt = 0; nt < 4; nt++) {
                    int col = n0 + wN + nt * 8 + (lane & 3) * 2;
                    float2 v;
                    v.x = acc[mt][nt][h * 2]     + bb[nt].x;
                    v.y = acc[mt][nt][h * 2 + 1] + bb[nt].y;
                    if (Uf) {
                        float2 u = *reinterpret_cast<const float2*>(Uf + urow * 1024 + col);
                        v.x += u.x; v.y += u.y;
                    }
                    *reinterpret_cast<float2*>(Cf + crow * 1024 + col) = v;
                }
            }
    } else {
#pragma unroll
        for (int mt = 0; mt < 4; mt++)
#pragma unroll
            for (int h = 0; h < 2; h++) {
                int row = m0 + wM + mt * 16 + (lane >> 2) + h * 8;
                size_t crow = (size_t)((row >> 6) * c0 + (row & 63) * c1 + c2);
                size_t urow = (size_t)((row >> 6) * u0 + (row & 63) * u1 + u2);
#pragma unroll
                for (int nt = 0; nt < 4; nt++) {
                    int col = n0 + wN + nt * 8 + (lane & 3) * 2;
                    float2 u = *reinterpret_cast<const float2*>(Uf + urow * 1024 + col);
                    float vx = acc[mt][nt][h * 2]     + u.x;
                    float vy = acc[mt][nt][h * 2 + 1] + u.y;
                    unsigned short hx = f2bh(vx), lx = f2bl(vx, hx);
                    unsigned short hy = f2bh(vy), ly = f2bl(vy, hy);
                    ushort2 hv = {hx, hy}, lv = {lx, ly};
                    *reinterpret_cast<ushort2*>(Chi + crow * 1024 + col) = hv;
                    *reinterpret_cast<ushort2*>(Clo + crow * 1024 + col) = lv;
                }
            }
    }
}

// ---------------- launch ----------------
extern "C" void kernel_launch(void* const* d_in, const int* in_sizes, int n_in,
                              void* d_out, int out_size)
{
    const float* X   = (const float*)d_in[0];
    const float* Wax = (const float*)d_in[1];
    const float* Waa = (const float*)d_in[2];
    const float* ba  = (const float*)d_in[3];
    const float* Wy  = (const float*)d_in[4];
    const float* by  = (const float*)d_in[5];
    float* out = (float*)d_out;

    cudaFuncSetAttribute(gmma<0>, cudaFuncAttributeMaxDynamicSharedMemorySize, GSMEM);
    cudaFuncSetAttribute(gmma<1>, cudaFuncAttributeMaxDynamicSharedMemorySize, GSMEM);

    const int n4x = RM * RACT / 4;
    const int n4w = RACT * RACT / 4;

    split_rt<<<n4x / 256, 256>>>((const float4*)X, (ushort4*)g_Xhi, (ushort4*)g_Xlo, n4x);
    split_rt<<<n4w / 256, 256>>>((const float4*)Wax, (ushort4*)g_W1hi, (ushort4*)g_W1lo, n4w);
    split_rt<<<n4w / 256, 256>>>((const float4*)Wy, (ushort4*)g_W2hi, (ushort4*)g_W2lo, n4w);
    split_rt<<<n4w / 256, 256>>>((const float4*)Waa, (ushort4*)g_W3hi, (ushort4*)g_W3lo, n4w);

    // GEMM1: U = X @ Wax^T + ba
    gmma<0><<<dim3(8, 256), 256, GSMEM>>>(g_Xhi, g_Xlo, g_W1hi, g_W1lo, ba, g_U,
                                          nullptr, nullptr, nullptr,
                                          1, 512, 0, 64, 1, 0, 0, 0, 0);

    // power chain: M_k = (W^T)^(2^k) (as row-major (W^(2^k))^T), N_k = W^(2^k)
    tns<<<4096, 256>>>(Waa, g_Mhi, g_Mlo);                 // M_0 = W^T
    gmma<0><<<dim3(8, 8), 256, GSMEM>>>(g_Mhi, g_Mlo, g_W3hi, g_W3lo, nullptr, g_F,
                                        nullptr, nullptr, nullptr,
                                        64, 1, 0, 64, 1, 0, 0, 0, 0);   // (W^2)^T
    gmma<0><<<dim3(8, 8), 256, GSMEM>>>(g_W3hi, g_W3lo, g_Mhi, g_Mlo, nullptr, g_F2,
                                        nullptr, nullptr, nullptr,
                                        64, 1, 0, 64, 1, 0, 0, 0, 0);   // W^2
    split_rt<<<n4w / 256, 256>>>((const float4*)g_F,  (ushort4*)g_Mhi, (ushort4*)g_Mlo, n4w);
    split_rt<<<n4w / 256, 256>>>((const float4*)g_F2, (ushort4*)g_Nhi, (ushort4*)g_Nlo, n4w);
    for (int q = 0; q < 3; q++) {   // -> ^4, ^8, ^16
        gmma<0><<<dim3(8, 8), 256, GSMEM>>>(g_Mhi, g_Mlo, g_Nhi, g_Nlo, nullptr, g_F,
                                            nullptr, nullptr, nullptr,
                                            64, 1, 0, 64, 1, 0, 0, 0, 0);
        gmma<0><<<dim3(8, 8), 256, GSMEM>>>(g_Nhi, g_Nlo, g_Mhi, g_Mlo, nullptr, g_F2,
                                            nullptr, nullptr, nullptr,
                                            64, 1, 0, 64, 1, 0, 0, 0, 0);
        split_rt<<<n4w / 256, 256>>>((const float4*)g_F,  (ushort4*)g_Mhi, (ushort4*)g_Mlo, n4w);
        split_rt<<<n4w / 256, 256>>>((const float4*)g_F2, (ushort4*)g_Nhi, (ushort4*)g_Nlo, n4w);
    }
    // g_N = W^16 (row-major [n][k])

    // pass 1: local recurrence (zero init); states i=0..14 into g_A rows c*1024+i*64+b
    split_gatherA<<<MP * 256 / 256, 256>>>();
    for (int i = 1; i < CHUNK - 1; i++) {
        gmma<1><<<dim3(8, 16), 256, GSMEM>>>(g_Ahi, g_Alo, g_W3hi, g_W3lo, nullptr, nullptr,
                                             g_Ahi, g_Alo, g_U,
                                             1024, 1, (i - 1) * 64,
                                             1024, 1, i * 64,
                                             1024, 1, i * 64);
    }
    // i = 15: v_c = l_15 -> fp32 g_V rows c*64+b
    gmma<0><<<dim3(8, 16), 256, GSMEM>>>(g_Ahi, g_Alo, g_W3hi, g_W3lo, nullptr, g_V,
                                         nullptr, nullptr, g_U,
                                         1024, 1, 14 * 64,
                                         64, 1, 0,
                                         1024, 1, 15 * 64);

    // boundary scan: s_c = v_c + s_{c-1} @ (W^16)^T, 32 sequential proven-gmma launches
    zero_bnd<<<64, 256>>>();
    for (int c = 0; c < NCHUNK; c++) {
        gmma<1><<<dim3(8, 1), 256, GSMEM>>>(g_Bndhi, g_Bndlo, g_Nhi, g_Nlo, nullptr, nullptr,
                                            g_Bndhi, g_Bndlo, g_V,
                                            0, 1, c * 64,
                                            0, 1, (c + 1) * 64,
                                            0, 1, c * 64);
    }

    // pass 2: corrected recurrence, overwrites g_A in place
    for (int i = 0; i < CHUNK; i++) {
        const __nv_bfloat16* sh = (i == 0) ? g_Bndhi : g_Ahi;
        const __nv_bfloat16* sl = (i == 0) ? g_Bndlo : g_Alo;
        int a0 = (i == 0) ? 64 : 1024;
        int a2 = (i == 0) ? 0 : (i - 1) * 64;
        gmma<1><<<dim3(8, 16), 256, GSMEM>>>(sh, sl, g_W3hi, g_W3lo, nullptr, nullptr,
                                             g_Ahi, g_Alo, g_U,
                                             a0, 1, a2, 1024, 1, i * 64, 1024, 1, i * 64);
    }

    // GEMM3: out[b][t] = a_t[b] @ Wy^T + by
    gmma<0><<<dim3(8, 256), 256, GSMEM>>>(g_Ahi, g_Alo, g_W2hi, g_W2lo, by, out,
                                          nullptr, nullptr, nullptr,
                                          64, 1, 0, 1, 512, 0, 0, 0, 0);
}

// round 7
// speedup vs baseline: 14.8478x; 14.8478x over previous
#include <cuda_runtime.h>
#include <cuda_bf16.h>
#include <cstdint>

#define RB   64
#define RT   512
#define RACT 1024
#define RM   (RT * RB)          // 32768
#define NBLK_REC 128
#define KSPLIT   8              // recurrence K-slices (128 k each)

#define N4X (RM * RACT / 4)     // 8388608 float4
#define N4W (RACT * RACT / 4)   // 262144 float4

// ---------------- scratch (device globals: allocation-free) ----------------
__device__ __align__(256) float g_U[RM * RACT];          // U[t][b][i] fp32
__device__ __align__(256) float g_P[KSPLIT * RB * RACT]; // per-step partials
__device__ unsigned int g_count;
__device__ volatile unsigned int g_gen;

// bf16 hi/lo split buffers
__device__ __align__(256) __nv_bfloat16 g_Xhi[RM * RACT];
__device__ __align__(256) __nv_bfloat16 g_Xlo[RM * RACT];
__device__ __align__(256) __nv_bfloat16 g_Ahi[RM * RACT];   // a_t split (written by recurrence)
__device__ __align__(256) __nv_bfloat16 g_Alo[RM * RACT];
__device__ __align__(256) __nv_bfloat16 g_W1hi[RACT * RACT];  // Wax
__device__ __align__(256) __nv_bfloat16 g_W1lo[RACT * RACT];
__device__ __align__(256) __nv_bfloat16 g_W2hi[RACT * RACT];  // Wy
__device__ __align__(256) __nv_bfloat16 g_W2lo[RACT * RACT];
__device__ __align__(256) __nv_bfloat16 g_W3hi[RACT * RACT];  // Waa
__device__ __align__(256) __nv_bfloat16 g_W3lo[RACT * RACT];

// ---------------- PTX helpers (portable: sm_80/75 features) ----------------
__device__ __forceinline__ uint32_t s2u(const void* p) {
    uint32_t a;
    asm("{ .reg .u64 t; cvta.to.shared.u64 t, %1; cvt.u32.u64 %0, t; }" : "=r"(a) : "l"(p));
    return a;
}
__device__ __forceinline__ void cpa16(uint32_t d, const void* s) {
    asm volatile("cp.async.cg.shared.global [%0], [%1], 16;\n" :: "r"(d), "l"(s));
}
__device__ __forceinline__ void cp_commit() { asm volatile("cp.async.commit_group;\n" ::: "memory"); }
template <int N> __device__ __forceinline__ void cp_wait() {
    asm volatile("cp.async.wait_group %0;\n" :: "n"(N) : "memory");
}
__device__ __forceinline__ void ldsm4(uint32_t& r0, uint32_t& r1, uint32_t& r2, uint32_t& r3,
                                      uint32_t addr) {
    asm volatile("ldmatrix.sync.aligned.m8n8.x4.shared.b16 {%0,%1,%2,%3}, [%4];"
                 : "=r"(r0), "=r"(r1), "=r"(r2), "=r"(r3) : "r"(addr));
}
__device__ __forceinline__ void mma16816(float* c, const uint32_t* a, const uint32_t* b) {
    asm volatile(
        "mma.sync.aligned.m16n8k16.row.col.f32.bf16.bf16.f32 "
        "{%0,%1,%2,%3}, {%4,%5,%6,%7}, {%8,%9}, {%0,%1,%2,%3};"
        : "+f"(c[0]), "+f"(c[1]), "+f"(c[2]), "+f"(c[3])
        : "r"(a[0]), "r"(a[1]), "r"(a[2]), "r"(a[3]), "r"(b[0]), "r"(b[1]));
}
__device__ __forceinline__ float4 ldcg4(const float* p) {
    return __ldcg(reinterpret_cast<const float4*>(p));
}

// ---------------- grid barrier (128 blocks, replay-safe) ----------------
__device__ __forceinline__ void grid_barrier() {
    __threadfence();
    __syncthreads();
    if (threadIdx.x == 0) {
        unsigned gen = g_gen;
        unsigned old = atomicAdd(&g_count, 1u);
        if (old == NBLK_REC - 1) {
            g_count = 0;
            __threadfence();
            g_gen = gen + 1;
        } else {
            while (g_gen == gen) { __nanosleep(64); }
        }
    }
    __syncthreads();
    __threadfence();
}

// ---------------- split helpers ----------------
__device__ __forceinline__ unsigned short f2bh(float x) {
    return __bfloat16_as_ushort(__float2bfloat16(x));
}
__device__ __forceinline__ unsigned short f2bl(float x, unsigned short h) {
    return __bfloat16_as_ushort(__float2bfloat16(x - __bfloat162float(__ushort_as_bfloat16(h))));
}

// ONE launch splits X, Wax, Wy, Waa (flat index over concatenated ranges)
__global__ void split_all(const float4* __restrict__ X,
                          const float4* __restrict__ W1,
                          const float4* __restrict__ W2,
                          const float4* __restrict__ W3)
{
    int i = blockIdx.x * blockDim.x + threadIdx.x;
    const float4* src;
    ushort4 *hi, *lo;
    int off;
    if (i < N4X) {
        src = X; off = i;
        hi = (ushort4*)g_Xhi; lo = (ushort4*)g_Xlo;
    } else {
        int j = i - N4X;
        int w = j / N4W;           // 0,1,2
        off   = j - w * N4W;
        if (w == 0)      { src = W1; hi = (ushort4*)g_W1hi; lo = (ushort4*)g_W1lo; }
        else if (w == 1) { src = W2; hi = (ushort4*)g_W2hi; lo = (ushort4*)g_W2lo; }
        else             { src = W3; hi = (ushort4*)g_W3hi; lo = (ushort4*)g_W3lo; }
    }
    float4 v = src[off];
    ushort4 h, l;
    h.x = f2bh(v.x); l.x = f2bl(v.x, h.x);
    h.y = f2bh(v.y); l.y = f2bl(v.y, h.y);
    h.z = f2bh(v.z); l.z = f2bl(v.z, h.z);
    h.w = f2bh(v.w); l.w = f2bl(v.w, h.w);
    hi[off] = h; lo[off] = l;
}

// ---------------- HMMA GEMM (verbatim round 3): C = A*B^T + bias ----------------
// bf16x3: Ahi*Bhi + Ahi*Blo + Alo*Bhi, fp32 register accumulators.
// CTA 128m x 128n x 32k/stage, 3-stage cp.async, 8 warps (warp tile 64m x 32n).
// MODE 0: A = X split (row remap m -> (m&63)*512 + (m>>6)), B = Wax, C = g_U row m
// MODE 1: A = A split (row m),                              B = Wy,  C = Cext remapped
#define TILE_B  10240          // 128 rows x 80 B
#define STG_B   (4 * TILE_B)   // Ah, Al, Bh, Bl
#define GSMEM   (3 * STG_B)    // 122880

template <int MODE>
__global__ void __launch_bounds__(256, 1) gemm_mma(const float* __restrict__ bias,
                                                   float* __restrict__ Cext)
{
    extern __shared__ char smc[];
    const uint32_t sbase = s2u(smc);

    const __nv_bfloat16* Ahi = (MODE == 0) ? g_Xhi : g_Ahi;
    const __nv_bfloat16* Alo = (MODE == 0) ? g_Xlo : g_Alo;
    const __nv_bfloat16* Bhi = (MODE == 0) ? g_W1hi : g_W2hi;
    const __nv_bfloat16* Blo = (MODE == 0) ? g_W1lo : g_W2lo;
    float* Cm = (MODE == 0) ? g_U : Cext;

    const int tid  = threadIdx.x;
    const int wid  = tid >> 5, lane = tid & 31;
    const int n0   = blockIdx.x * 128, m0 = blockIdx.y * 128;
    const int wM   = (wid & 1) * 64;
    const int wN   = (wid >> 1) * 32;

    const char* srcp[8];
    uint32_t dsto[8];
#pragma unroll
    for (int i = 0; i < 8; i++) {
        int idx = i * 256 + tid;
        int buf = idx >> 9;              // 0 Ah, 1 Al, 2 Bh, 3 Bl
        int r   = (idx >> 2) & 127;
        int s   = idx & 3;
        dsto[i] = (uint32_t)(buf * TILE_B + r * 80 + s * 16);
        size_t grow;
        const __nv_bfloat16* p;
        if (buf < 2) {
            int row = m0 + r;
            grow = (MODE == 0) ? (size_t)(((row & 63) << 9) | (row >> 6)) : (size_t)row;
            p = (buf == 0) ? Ahi : Alo;
        } else {
            grow = (size_t)(n0 + r);
            p = (buf == 2) ? Bhi : Blo;
        }
        srcp[i] = (const char*)p + grow * 2048 + s * 16;
    }

#pragma unroll
    for (int st = 0; st < 2; st++) {
#pragma unroll
        for (int i = 0; i < 8; i++)
            cpa16(sbase + st * STG_B + dsto[i], srcp[i] + st * 64);
        cp_commit();
    }

    float acc[4][4][4];
#pragma unroll
    for (int a = 0; a < 4; a++)
#pragma unroll
        for (int b = 0; b < 4; b++)
#pragma unroll
            for (int c = 0; c < 4; c++) acc[a][b][c] = 0.f;

    const int j   = lane >> 3;
    const int arl = (lane & 7) + (j & 1) * 8;
    const int brl = (lane & 7) + (j >> 1) * 8;

    for (int c = 0; c < 32; c++) {
        cp_wait<1>();
        __syncthreads();
        if (c + 2 < 32) {
            uint32_t sb2 = sbase + ((c + 2) % 3) * STG_B;
#pragma unroll
            for (int i = 0; i < 8; i++)
                cpa16(sb2 + dsto[i], srcp[i] + (c + 2) * 64);
        }
        cp_commit();

        const uint32_t sb = sbase + (c % 3) * STG_B;
#pragma unroll
        for (int kt = 0; kt < 2; kt++) {
            const int aseg = kt * 2 + (j >> 1);
            const int bseg = kt * 2 + (j & 1);
            uint32_t ah[4][4], al[4][4];
#pragma unroll
            for (int mt = 0; mt < 4; mt++) {
                uint32_t ra = sb + (uint32_t)((wM + mt * 16 + arl) * 80 + aseg * 16);
                ldsm4(ah[mt][0], ah[mt][1], ah[mt][2], ah[mt][3], ra);
                ldsm4(al[mt][0], al[mt][1], al[mt][2], al[mt][3], ra + TILE_B);
            }
            uint32_t bh[4][2], bl[4][2];
#pragma unroll
            for (int bt = 0; bt < 2; bt++) {
                uint32_t rb = sb + 2 * TILE_B + (uint32_t)((wN + bt * 16 + brl) * 80 + bseg * 16);
                uint32_t t0, t1, t2, t3;
                ldsm4(t0, t1, t2, t3, rb);
                bh[bt * 2][0] = t0; bh[bt * 2][1] = t1;
                bh[bt * 2 + 1][0] = t2; bh[bt * 2 + 1][1] = t3;
                ldsm4(t0, t1, t2, t3, rb + TILE_B);
                bl[bt * 2][0] = t0; bl[bt * 2][1] = t1;
                bl[bt * 2 + 1][0] = t2; bl[bt * 2 + 1][1] = t3;
            }
#pragma unroll
            for (int mt = 0; mt < 4; mt++)
#pragma unroll
                for (int nt = 0; nt < 4; nt++) {
                    mma16816(acc[mt][nt], ah[mt], bh[nt]);
                    mma16816(acc[mt][nt], ah[mt], bl[nt]);
                    mma16816(acc[mt][nt], al[mt], bh[nt]);
                }
        }
    }

    float2 bb[4];
#pragma unroll
    for (int nt = 0; nt < 4; nt++) {
        int col = n0 + wN + nt * 8 + (lane & 3) * 2;
        bb[nt].x = bias[col]; bb[nt].y = bias[col + 1];
    }
#pragma unroll
    for (int mt = 0; mt < 4; mt++)
#pragma unroll
        for (int h = 0; h < 2; h++) {
            int row  = m0 + wM + mt * 16 + (lane >> 2) + h * 8;
            size_t crow = (MODE == 0) ? (size_t)row
                                      : (size_t)(((row & 63) << 9) | (row >> 6));
#pragma unroll
            for (int nt = 0; nt < 4; nt++) {
                int col = n0 + wN + nt * 8 + (lane & 3) * 2;
                float2 v;
                v.x = acc[mt][nt][h * 2]     + bb[nt].x;
                v.y = acc[mt][nt][h * 2 + 1] + bb[nt].y;
                *reinterpret_cast<float2*>(Cm + crow * 1024 + col) = v;
            }
        }
}

// ---------------- HMMA recurrence (verbatim round 3) ----------------
// 128 blocks = 16 N-tiles (64 n) x 8 K-slices (128 k), 128 threads (4 warps).
#define RROW 272
#define R_AH 0
#define R_AL (64 * RROW)
#define R_WH (2 * 64 * RROW)
#define R_WL (3 * 64 * RROW)
#define RSMEM (4 * 64 * RROW)   // 69632

__global__ void __launch_bounds__(128, 1) rnn_rec_mma()
{
    extern __shared__ char smc[];
    const uint32_t sbase = s2u(smc);

    const int tid = threadIdx.x, wid = tid >> 5, lane = tid & 31;
    const int bx  = blockIdx.x;
    const int nb  = bx & 15, ks = bx >> 4;
    const int n0  = nb * 64;
    const int kb0 = ks * 256;          // byte offset of K-slice in a 2048B row

    // load Waa hi/lo slice once
#pragma unroll
    for (int i = 0; i < 16; i++) {
        int idx = i * 128 + tid;
        int buf = idx >> 10, r = (idx >> 4) & 63, s = idx & 15;
        uint32_t dst = sbase + (buf ? R_WL : R_WH) + (uint32_t)(r * RROW + s * 16);
        const char* src = (const char*)(buf ? g_W3lo : g_W3hi)
                        + (size_t)(n0 + r) * 2048 + kb0 + s * 16;
        cpa16(dst, src);
    }
    cp_commit();
    cp_wait<0>();
    __syncthreads();

    const int j   = lane >> 3;
    const int arl = (lane & 7) + (j & 1) * 8;
    const int brl = (lane & 7) + (j >> 1) * 8;
    float* Pp = g_P + (size_t)ks * (RB * RACT);

    for (int t = 0; t < RT; ++t) {
        if (t > 0) {
#pragma unroll
            for (int i = 0; i < 16; i++) {
                int idx = i * 128 + tid;
                int buf = idx >> 10, r = (idx >> 4) & 63, s = idx & 15;
                uint32_t dst = sbase + (buf ? R_AL : R_AH) + (uint32_t)(r * RROW + s * 16);
                const char* src = (const char*)(buf ? g_Alo : g_Ahi)
                                + (size_t)((t - 1) * 64 + r) * 2048 + kb0 + s * 16;
                cpa16(dst, src);
            }
            cp_commit();
            cp_wait<0>();
            __syncthreads();

            float acc[4][2][4];
#pragma unroll
            for (int a = 0; a < 4; a++)
#pragma unroll
                for (int b = 0; b < 2; b++)
#pragma unroll
                    for (int c = 0; c < 4; c++) acc[a][b][c] = 0.f;

#pragma unroll
            for (int kt = 0; kt < 8; kt++) {
                const int aseg = kt * 2 + (j >> 1);
                const int bseg = kt * 2 + (j & 1);
                uint32_t ah[4][4], al[4][4];
#pragma unroll
                for (int mt = 0; mt < 4; mt++) {
                    uint32_t ra = sbase + R_AH + (uint32_t)((mt * 16 + arl) * RROW + aseg * 16);
                    ldsm4(ah[mt][0], ah[mt][1], ah[mt][2], ah[mt][3], ra);
                    ldsm4(al[mt][0], al[mt][1], al[mt][2], al[mt][3], ra + (R_AL - R_AH));
                }
                uint32_t bh[2][2], bl[2][2];
                {
                    uint32_t rb = sbase + R_WH + (uint32_t)((wid * 16 + brl) * RROW + bseg * 16);
                    uint32_t t0, t1, t2, t3;
                    ldsm4(t0, t1, t2, t3, rb);
                    bh[0][0] = t0; bh[0][1] = t1; bh[1][0] = t2; bh[1][1] = t3;
                    ldsm4(t0, t1, t2, t3, rb + (R_WL - R_WH));
                    bl[0][0] = t0; bl[0][1] = t1; bl[1][0] = t2; bl[1][1] = t3;
                }
#pragma unroll
                for (int mt = 0; mt < 4; mt++)
#pragma unroll
                    for (int nt = 0; nt < 2; nt++) {
                        mma16816(acc[mt][nt], ah[mt], bh[nt]);
                        mma16816(acc[mt][nt], ah[mt], bl[nt]);
                        mma16816(acc[mt][nt], al[mt], bh[nt]);
                    }
            }

#pragma unroll
            for (int mt = 0; mt < 4; mt++)
#pragma unroll
                for (int h = 0; h < 2; h++) {
                    int b = mt * 16 + (lane >> 2) + h * 8;
#pragma unroll
                    for (int nt = 0; nt < 2; nt++) {
                        int icol = n0 + wid * 16 + nt * 8 + (lane & 3) * 2;
                        float2 v;
                        v.x = acc[mt][nt][h * 2];
                        v.y = acc[mt][nt][h * 2 + 1];
                        *reinterpret_cast<float2*>(Pp + (size_t)b * 1024 + icol) = v;
                    }
                }
        }

        grid_barrier();

        {
            const int base = bx * 512 + tid * 4;
            float4 s4 = *reinterpret_cast<const float4*>(g_U + (size_t)t * (RB * RACT) + base);
            if (t > 0) {
#pragma unroll
                for (int p = 0; p < KSPLIT; ++p) {
                    float4 v = ldcg4(g_P + (size_t)p * (RB * RACT) + base);
                    s4.x += v.x; s4.y += v.y; s4.z += v.z; s4.w += v.w;
                }
            }
            ushort4 h4, l4;
            h4.x = f2bh(s4.x); l4.x = f2bl(s4.x, h4.x);
            h4.y = f2bh(s4.y); l4.y = f2bl(s4.y, h4.y);
            h4.z = f2bh(s4.z); l4.z = f2bl(s4.z, h4.z);
            h4.w = f2bh(s4.w); l4.w = f2bl(s4.w, h4.w);
            const size_t e = (size_t)t * (RB * RACT) + base;
            *reinterpret_cast<ushort4*>(&g_Ahi[e]) = h4;
            *reinterpret_cast<ushort4*>(&g_Alo[e]) = l4;
        }

        grid_barrier();
    }
}

// ---------------- launch: 4 nodes total ----------------
extern "C" void kernel_launch(void* const* d_in, const int* in_sizes, int n_in,
                              void* d_out, int out_size)
{
    const float* X   = (const float*)d_in[0];
    const float* Wax = (const float*)d_in[1];
    const float* Waa = (const float*)d_in[2];
    const float* ba  = (const float*)d_in[3];
    const float* Wy  = (const float*)d_in[4];
    const float* by  = (const float*)d_in[5];
    float* out = (float*)d_out;

    cudaFuncSetAttribute(gemm_mma<0>, cudaFuncAttributeMaxDynamicSharedMemorySize, GSMEM);
    cudaFuncSetAttribute(gemm_mma<1>, cudaFuncAttributeMaxDynamicSharedMemorySize, GSMEM);
    cudaFuncSetAttribute(rnn_rec_mma, cudaFuncAttributeMaxDynamicSharedMemorySize, RSMEM);

    const int ntot = N4X + 3 * N4W;      // 9,175,040 float4

    split_all<<<ntot / 256, 256>>>((const float4*)X, (const float4*)Wax,
                                   (const float4*)Wy, (const float4*)Waa);

    gemm_mma<0><<<dim3(8, 256), 256, GSMEM>>>(ba, nullptr);   // U = X @ Wax^T + ba
    rnn_rec_mma<<<NBLK_REC, 128, RSMEM>>>();                  // a_t (bf16 hi/lo split)
    gemm_mma<1><<<dim3(8, 256), 256, GSMEM>>>(by, out);       // out = A @ Wy^T + by
}

// round 8
// speedup vs baseline: 21.7545x; 1.4652x over previous
#include <cuda_runtime.h>
#include <cuda_bf16.h>
#include <cstdint>

#define RB     64
#define RT     512
#define RACT   1024
#define RM     (RT * RB)        // 32768
#define CHUNK  16
#define NCHUNK 32
#define MP     (NCHUNK * RB)    // 2048
#define NBLK   128
#define KSPLIT 8

#define N4X (RM * RACT / 4)
#define N4W (RACT * RACT / 4)

// ---------------- scratch (device globals: allocation-free) ----------------
__device__ __align__(256) float g_U[RM * RACT];
__device__ __align__(256) float g_V[MP * RACT];            // v_c fp32
__device__ __align__(256) float g_P[KSPLIT * RB * RACT];   // boundary partials
__device__ unsigned int g_count;
__device__ volatile unsigned int g_gen;

__device__ __align__(256) __nv_bfloat16 g_Xhi[RM * RACT],  g_Xlo[RM * RACT];
__device__ __align__(256) __nv_bfloat16 g_Ahi[RM * RACT],  g_Alo[RM * RACT];
__device__ __align__(256) __nv_bfloat16 g_W1hi[RACT * RACT], g_W1lo[RACT * RACT]; // Wax
__device__ __align__(256) __nv_bfloat16 g_W2hi[RACT * RACT], g_W2lo[RACT * RACT]; // Wy
__device__ __align__(256) __nv_bfloat16 g_W3hi[RACT * RACT], g_W3lo[RACT * RACT]; // Waa
__device__ __align__(256) __nv_bfloat16 g_Mhi[RACT * RACT],  g_Mlo[RACT * RACT];
__device__ __align__(256) __nv_bfloat16 g_M2hi[RACT * RACT], g_M2lo[RACT * RACT];
__device__ __align__(256) __nv_bfloat16 g_Nhi[RACT * RACT],  g_Nlo[RACT * RACT];
__device__ __align__(256) __nv_bfloat16 g_N2hi[RACT * RACT], g_N2lo[RACT * RACT];
__device__ __align__(256) __nv_bfloat16 g_Bndhi[(NCHUNK + 1) * RB * RACT];
__device__ __align__(256) __nv_bfloat16 g_Bndlo[(NCHUNK + 1) * RB * RACT];

// ---------------- PTX helpers ----------------
__device__ __forceinline__ uint32_t s2u(const void* p) {
    uint32_t a;
    asm("{ .reg .u64 t; cvta.to.shared.u64 t, %1; cvt.u32.u64 %0, t; }" : "=r"(a) : "l"(p));
    return a;
}
__device__ __forceinline__ void cpa16(uint32_t d, const void* s) {
    asm volatile("cp.async.cg.shared.global [%0], [%1], 16;\n" :: "r"(d), "l"(s));
}
__device__ __forceinline__ void cp_commit() { asm volatile("cp.async.commit_group;\n" ::: "memory"); }
template <int N> __device__ __forceinline__ void cp_wait() {
    asm volatile("cp.async.wait_group %0;\n" :: "n"(N) : "memory");
}
__device__ __forceinline__ void ldsm4(uint32_t& r0, uint32_t& r1, uint32_t& r2, uint32_t& r3,
                                      uint32_t addr) {
    asm volatile("ldmatrix.sync.aligned.m8n8.x4.shared.b16 {%0,%1,%2,%3}, [%4];"
                 : "=r"(r0), "=r"(r1), "=r"(r2), "=r"(r3) : "r"(addr));
}
__device__ __forceinline__ void mma16816(float* c, const uint32_t* a, const uint32_t* b) {
    asm volatile(
        "mma.sync.aligned.m16n8k16.row.col.f32.bf16.bf16.f32 "
        "{%0,%1,%2,%3}, {%4,%5,%6,%7}, {%8,%9}, {%0,%1,%2,%3};"
        : "+f"(c[0]), "+f"(c[1]), "+f"(c[2]), "+f"(c[3])
        : "r"(a[0]), "r"(a[1]), "r"(a[2]), "r"(a[3]), "r"(b[0]), "r"(b[1]));
}
__device__ __forceinline__ float4 ldcg4(const float* p) {
    return __ldcg(reinterpret_cast<const float4*>(p));
}

// ---------------- grid barrier (128 blocks, replay-safe) ----------------
__device__ __forceinline__ void grid_barrier() {
    __threadfence();
    __syncthreads();
    if (threadIdx.x == 0) {
        unsigned gen = g_gen;
        unsigned old = atomicAdd(&g_count, 1u);
        if (old == NBLK - 1) {
            g_count = 0;
            __threadfence();
            g_gen = gen + 1;
        } else {
            while (g_gen == gen) { __nanosleep(64); }
        }
    }
    __syncthreads();
    __threadfence();
}

// ---------------- split helpers ----------------
__device__ __forceinline__ unsigned short f2bh(float x) {
    return __bfloat16_as_ushort(__float2bfloat16(x));
}
__device__ __forceinline__ unsigned short f2bl(float x, unsigned short h) {
    return __bfloat16_as_ushort(__float2bfloat16(x - __bfloat162float(__ushort_as_bfloat16(h))));
}

__global__ void split_all(const float4* __restrict__ X,
                          const float4* __restrict__ W1,
                          const float4* __restrict__ W2,
                          const float4* __restrict__ W3)
{
    int i = blockIdx.x * blockDim.x + threadIdx.x;
    const float4* src;
    ushort4 *hi, *lo;
    int off;
    if (i < N4X) {
        src = X; off = i;
        hi = (ushort4*)g_Xhi; lo = (ushort4*)g_Xlo;
    } else {
        int j = i - N4X;
        int w = j / N4W;
        off   = j - w * N4W;
        if (w == 0)      { src = W1; hi = (ushort4*)g_W1hi; lo = (ushort4*)g_W1lo; }
        else if (w == 1) { src = W2; hi = (ushort4*)g_W2hi; lo = (ushort4*)g_W2lo; }
        else             { src = W3; hi = (ushort4*)g_W3hi; lo = (ushort4*)g_W3lo; }
    }
    float4 v = src[off];
    ushort4 h, l;
    h.x = f2bh(v.x); l.x = f2bl(v.x, h.x);
    h.y = f2bh(v.y); l.y = f2bl(v.y, h.y);
    h.z = f2bh(v.z); l.z = f2bl(v.z, h.z);
    h.w = f2bh(v.w); l.w = f2bl(v.w, h.w);
    hi[off] = h; lo[off] = l;
}

// ---------------- standalone HMMA GEMM (verbatim R7) ----------------
#define TILE_B  10240
#define STG_B   (4 * TILE_B)
#define GSMEM   (3 * STG_B)

template <int MODE>
__global__ void __launch_bounds__(256, 1) gemm_mma(const float* __restrict__ bias,
                                                   float* __restrict__ Cext)
{
    extern __shared__ char smc[];
    const uint32_t sbase = s2u(smc);

    const __nv_bfloat16* Ahi = (MODE == 0) ? g_Xhi : g_Ahi;
    const __nv_bfloat16* Alo = (MODE == 0) ? g_Xlo : g_Alo;
    const __nv_bfloat16* Bhi = (MODE == 0) ? g_W1hi : g_W2hi;
    const __nv_bfloat16* Blo = (MODE == 0) ? g_W1lo : g_W2lo;
    float* Cm = (MODE == 0) ? g_U : Cext;

    const int tid  = threadIdx.x;
    const int wid  = tid >> 5, lane = tid & 31;
    const int n0   = blockIdx.x * 128, m0 = blockIdx.y * 128;
    const int wM   = (wid & 1) * 64;
    const int wN   = (wid >> 1) * 32;

    const char* srcp[8];
    uint32_t dsto[8];
#pragma unroll
    for (int i = 0; i < 8; i++) {
        int idx = i * 256 + tid;
        int buf = idx >> 9;
        int r   = (idx >> 2) & 127;
        int s   = idx & 3;
        dsto[i] = (uint32_t)(buf * TILE_B + r * 80 + s * 16);
        size_t grow;
        const __nv_bfloat16* p;
        if (buf < 2) {
            int row = m0 + r;
            grow = (MODE == 0) ? (size_t)(((row & 63) << 9) | (row >> 6)) : (size_t)row;
            p = (buf == 0) ? Ahi : Alo;
        } else {
            grow = (size_t)(n0 + r);
            p = (buf == 2) ? Bhi : Blo;
        }
        srcp[i] = (const char*)p + grow * 2048 + s * 16;
    }

#pragma unroll
    for (int st = 0; st < 2; st++) {
#pragma unroll
        for (int i = 0; i < 8; i++)
            cpa16(sbase + st * STG_B + dsto[i], srcp[i] + st * 64);
        cp_commit();
    }

    float acc[4][4][4];
#pragma unroll
    for (int a = 0; a < 4; a++)
#pragma unroll
        for (int b = 0; b < 4; b++)
#pragma unroll
            for (int c = 0; c < 4; c++) acc[a][b][c] = 0.f;

    const int j   = lane >> 3;
    const int arl = (lane & 7) + (j & 1) * 8;
    const int brl = (lane & 7) + (j >> 1) * 8;

    for (int c = 0; c < 32; c++) {
        cp_wait<1>();
        __syncthreads();
        if (c + 2 < 32) {
            uint32_t sb2 = sbase + ((c + 2) % 3) * STG_B;
#pragma unroll
            for (int i = 0; i < 8; i++)
                cpa16(sb2 + dsto[i], srcp[i] + (c + 2) * 64);
        }
        cp_commit();

        const uint32_t sb = sbase + (c % 3) * STG_B;
#pragma unroll
        for (int kt = 0; kt < 2; kt++) {
            const int aseg = kt * 2 + (j >> 1);
            const int bseg = kt * 2 + (j & 1);
            uint32_t ah[4][4], al[4][4];
#pragma unroll
            for (int mt = 0; mt < 4; mt++) {
                uint32_t ra = sb + (uint32_t)((wM + mt * 16 + arl) * 80 + aseg * 16);
                ldsm4(ah[mt][0], ah[mt][1], ah[mt][2], ah[mt][3], ra);
                ldsm4(al[mt][0], al[mt][1], al[mt][2], al[mt][3], ra + TILE_B);
            }
            uint32_t bh[4][2], bl[4][2];
#pragma unroll
            for (int bt = 0; bt < 2; bt++) {
                uint32_t rb = sb + 2 * TILE_B + (uint32_t)((wN + bt * 16 + brl) * 80 + bseg * 16);
                uint32_t t0, t1, t2, t3;
                ldsm4(t0, t1, t2, t3, rb);
                bh[bt * 2][0] = t0; bh[bt * 2][1] = t1;
                bh[bt * 2 + 1][0] = t2; bh[bt * 2 + 1][1] = t3;
                ldsm4(t0, t1, t2, t3, rb + TILE_B);
                bl[bt * 2][0] = t0; bl[bt * 2][1] = t1;
                bl[bt * 2 + 1][0] = t2; bl[bt * 2 + 1][1] = t3;
            }
#pragma unroll
            for (int mt = 0; mt < 4; mt++)
#pragma unroll
                for (int nt = 0; nt < 4; nt++) {
                    mma16816(acc[mt][nt], ah[mt], bh[nt]);
                    mma16816(acc[mt][nt], ah[mt], bl[nt]);
                    mma16816(acc[mt][nt], al[mt], bh[nt]);
                }
        }
    }

    float2 bb[4];
#pragma unroll
    for (int nt = 0; nt < 4; nt++) {
        int col = n0 + wN + nt * 8 + (lane & 3) * 2;
        bb[nt].x = bias[col]; bb[nt].y = bias[col + 1];
    }
#pragma unroll
    for (int mt = 0; mt < 4; mt++)
#pragma unroll
        for (int h = 0; h < 2; h++) {
            int row  = m0 + wM + mt * 16 + (lane >> 2) + h * 8;
            size_t crow = (MODE == 0) ? (size_t)row
                                      : (size_t)(((row & 63) << 9) | (row >> 6));
#pragma unroll
            for (int nt = 0; nt < 4; nt++) {
                int col = n0 + wN + nt * 8 + (lane & 3) * 2;
                float2 v;
                v.x = acc[mt][nt][h * 2]     + bb[nt].x;
                v.y = acc[mt][nt][h * 2 + 1] + bb[nt].y;
                *reinterpret_cast<float2*>(Cm + crow * 1024 + col) = v;
            }
        }
}

// ---------------- device-function 128x128 GEMM tile (same mainloop) ----------------
// C[m][n] = sum_k A[m][k] * B[n][k]  (bf16x3). A-row remap (r0,r1,r2); B rows plain n0+r.
// If Cf != null: fp32 store (+Uf). Else: bf16 split store (+Uf).
__device__ void g128(uint32_t sbase, int tid,
    const __nv_bfloat16* Ah, const __nv_bfloat16* Al,
    const __nv_bfloat16* Bh, const __nv_bfloat16* Bl,
    int m0, int n0, int a0, int a1, int a2,
    float* Cf, __nv_bfloat16* Chi, __nv_bfloat16* Clo,
    const float* Uf,
    int c0, int c1, int c2, int u0, int u1, int u2)
{
    const int wid = tid >> 5, lane = tid & 31;
    const int wM  = (wid & 1) * 64;
    const int wN  = (wid >> 1) * 32;

    const char* srcp[8];
    uint32_t dsto[8];
#pragma unroll
    for (int i = 0; i < 8; i++) {
        int idx = i * 256 + tid;
        int buf = idx >> 9;
        int r   = (idx >> 2) & 127;
        int s   = idx & 3;
        dsto[i] = (uint32_t)(buf * TILE_B + r * 80 + s * 16);
        size_t grow;
        const __nv_bfloat16* p;
        if (buf < 2) {
            int row = m0 + r;
            grow = (size_t)((row >> 6) * a0 + (row & 63) * a1 + a2);
            p = (buf == 0) ? Ah : Al;
        } else {
            grow = (size_t)(n0 + r);
            p = (buf == 2) ? Bh : Bl;
        }
        srcp[i] = (const char*)p + grow * 2048 + s * 16;
    }

#pragma unroll
    for (int st = 0; st < 2; st++) {
#pragma unroll
        for (int i = 0; i < 8; i++)
            cpa16(sbase + st * STG_B + dsto[i], srcp[i] + st * 64);
        cp_commit();
    }

    float acc[4][4][4];
#pragma unroll
    for (int a = 0; a < 4; a++)
#pragma unroll
        for (int b = 0; b < 4; b++)
#pragma unroll
            for (int c = 0; c < 4; c++) acc[a][b][c] = 0.f;

    const int j   = lane >> 3;
    const int arl = (lane & 7) + (j & 1) * 8;
    const int brl = (lane & 7) + (j >> 1) * 8;

    for (int c = 0; c < 32; c++) {
        cp_wait<1>();
        __syncthreads();
        if (c + 2 < 32) {
            uint32_t sb2 = sbase + ((c + 2) % 3) * STG_B;
#pragma unroll
            for (int i = 0; i < 8; i++)
                cpa16(sb2 + dsto[i], srcp[i] + (c + 2) * 64);
        }
        cp_commit();

        const uint32_t sb = sbase + (c % 3) * STG_B;
#pragma unroll
        for (int kt = 0; kt < 2; kt++) {
            const int aseg = kt * 2 + (j >> 1);
            const int bseg = kt * 2 + (j & 1);
            uint32_t ah[4][4], al[4][4];
#pragma unroll
            for (int mt = 0; mt < 4; mt++) {
                uint32_t ra = sb + (uint32_t)((wM + mt * 16 + arl) * 80 + aseg * 16);
                ldsm4(ah[mt][0], ah[mt][1], ah[mt][2], ah[mt][3], ra);
                ldsm4(al[mt][0], al[mt][1], al[mt][2], al[mt][3], ra + TILE_B);
            }
            uint32_t bh[4][2], bl[4][2];
#pragma unroll
            for (int bt = 0; bt < 2; bt++) {
                uint32_t rb = sb + 2 * TILE_B + (uint32_t)((wN + bt * 16 + brl) * 80 + bseg * 16);
                uint32_t t0, t1, t2, t3;
                ldsm4(t0, t1, t2, t3, rb);
                bh[bt * 2][0] = t0; bh[bt * 2][1] = t1;
                bh[bt * 2 + 1][0] = t2; bh[bt * 2 + 1][1] = t3;
                ldsm4(t0, t1, t2, t3, rb + TILE_B);
                bl[bt * 2][0] = t0; bl[bt * 2][1] = t1;
                bl[bt * 2 + 1][0] = t2; bl[bt * 2 + 1][1] = t3;
            }
#pragma unroll
            for (int mt = 0; mt < 4; mt++)
#pragma unroll
                for (int nt = 0; nt < 4; nt++) {
                    mma16816(acc[mt][nt], ah[mt], bh[nt]);
                    mma16816(acc[mt][nt], ah[mt], bl[nt]);
                    mma16816(acc[mt][nt], al[mt], bh[nt]);
                }
        }
    }
    cp_wait<0>();   // drain tail group before caller reuses smem

#pragma unroll
    for (int mt = 0; mt < 4; mt++)
#pragma unroll
        for (int h = 0; h < 2; h++) {
            int row = m0 + wM + mt * 16 + (lane >> 2) + h * 8;
            size_t crow = (size_t)((row >> 6) * c0 + (row & 63) * c1 + c2);
            size_t urow = (size_t)((row >> 6) * u0 + (row & 63) * u1 + u2);
#pragma unroll
            for (int nt = 0; nt < 4; nt++) {
                int col = n0 + wN + nt * 8 + (lane & 3) * 2;
                float vx = acc[mt][nt][h * 2];
                float vy = acc[mt][nt][h * 2 + 1];
                if (Uf) {
                    float2 u = *reinterpret_cast<const float2*>(Uf + urow * 1024 + col);
                    vx += u.x; vy += u.y;
                }
                if (Cf) {
                    float2 v; v.x = vx; v.y = vy;
                    *reinterpret_cast<float2*>(Cf + crow * 1024 + col) = v;
                } else {
                    unsigned short hx = f2bh(vx), lx = f2bl(vx, hx);
                    unsigned short hy = f2bh(vy), ly = f2bl(vy, hy);
                    ushort2 hv = {hx, hy}, lv = {lx, ly};
                    *reinterpret_cast<ushort2*>(Chi + crow * 1024 + col) = hv;
                    *reinterpret_cast<ushort2*>(Clo + crow * 1024 + col) = lv;
                }
            }
        }
}

// ---------------- persistent scan kernel ----------------
// P0: W^T split, U chunk-head split, zero Bnd
// P1: E = W^16 (4 dual-orientation squarings)
// P2: pass1 (15 macro-steps, i=15 -> fp32 g_V)
// P3: boundary scan (32 steps, K-split + reduce; R7 structure)
// P4: pass2 (16 macro-steps, exact states into g_A)
#define RROW 272
#define R_AH 0
#define R_AL (64 * RROW)
#define R_EH (2 * 64 * RROW)
#define R_EL (3 * 64 * RROW)

__global__ void __launch_bounds__(256, 1) scan_all(const float* __restrict__ Waa)
{
    extern __shared__ char smc[];
    const uint32_t sbase = s2u(smc);
    const int tid = threadIdx.x;
    const int bx  = blockIdx.x;
    const int gt  = bx * 256 + tid;           // 0..32767

    // ---- P0 ----
    for (int g = gt; g < 1024 * 1024; g += 32768) {      // M_0 = W^T split
        int jr = g >> 10, ir = g & 1023;
        float v = Waa[(size_t)ir * 1024 + jr];
        unsigned short h = f2bh(v), l = f2bl(v, h);
        g_Mhi[g] = __ushort_as_bfloat16(h);
        g_Mlo[g] = __ushort_as_bfloat16(l);
    }
    for (int g = gt; g < MP * 256; g += 32768) {         // chunk-head split (float4)
        int row = g >> 8, c4 = (g & 255) * 4;
        size_t off = ((size_t)((row >> 6) * 1024 + (row & 63))) * 1024 + c4;
        float4 v = *reinterpret_cast<const float4*>(g_U + off);
        ushort4 h, l;
        h.x = f2bh(v.x); l.x = f2bl(v.x, h.x);
        h.y = f2bh(v.y); l.y = f2bl(v.y, h.y);
        h.z = f2bh(v.z); l.z = f2bl(v.z, h.z);
        h.w = f2bh(v.w); l.w = f2bl(v.w, h.w);
        *reinterpret_cast<ushort4*>(g_Ahi + off) = h;
        *reinterpret_cast<ushort4*>(g_Alo + off) = l;
    }
    {
        ushort4 z = {0, 0, 0, 0};
        for (int g = gt; g < 16384; g += 32768) {        // zero Bnd rows 0..63
            reinterpret_cast<ushort4*>(g_Bndhi)[g] = z;
            reinterpret_cast<ushort4*>(g_Bndlo)[g] = z;
        }
    }
    grid_barrier();

    // ---- P1: E powers. L: rM,rN -> wM,wN ----
    {
        const __nv_bfloat16 *rMh[4] = {g_Mhi,  g_M2hi, g_Mhi,  g_M2hi};
        const __nv_bfloat16 *rMl[4] = {g_Mlo,  g_M2lo, g_Mlo,  g_M2lo};
        const __nv_bfloat16 *rNh[4] = {g_W3hi, g_N2hi, g_Nhi,  g_N2hi};
        const __nv_bfloat16 *rNl[4] = {g_W3lo, g_N2lo, g_Nlo,  g_N2lo};
        __nv_bfloat16 *wMh[4] = {g_M2hi, g_Mhi, g_M2hi, g_Mhi};
        __nv_bfloat16 *wMl[4] = {g_M2lo, g_Mlo, g_M2lo, g_Mlo};
        __nv_bfloat16 *wNh[4] = {g_N2hi, g_Nhi, g_N2hi, g_Nhi};
        __nv_bfloat16 *wNl[4] = {g_N2lo, g_Nlo, g_N2lo, g_Nlo};

        const int o  = bx >> 6;            // 0: M' = gmma(M,N), 1: N' = gmma(N,M)
        const int t6 = bx & 63;
        const int m0 = (t6 >> 3) * 128, n0 = (t6 & 7) * 128;
        for (int L = 0; L < 4; L++) {
            const __nv_bfloat16 *Ah = o ? rNh[L] : rMh[L], *Al = o ? rNl[L] : rMl[L];
            const __nv_bfloat16 *Bh = o ? rMh[L] : rNh[L], *Bl = o ? rMl[L] : rNl[L];
            __nv_bfloat16 *Ch = o ? wNh[L] : wMh[L], *Cl = o ? wNl[L] : wMl[L];
            g128(sbase, tid, Ah, Al, Bh, Bl, m0, n0, 64, 1, 0,
                 nullptr, Ch, Cl, nullptr, 64, 1, 0, 0, 0, 0);
            grid_barrier();
        }
    }
    // E = g_N (= W^16, rows [n][k])

    // ---- P2: pass1 ----
    {
        const int m0 = (bx >> 3) * 128, n0 = (bx & 7) * 128;
        for (int i = 1; i < CHUNK; i++) {
            if (i < CHUNK - 1) {
                g128(sbase, tid, g_Ahi, g_Alo, g_W3hi, g_W3lo, m0, n0,
                     1024, 1, (i - 1) * 64,
                     nullptr, g_Ahi, g_Alo, g_U,
                     1024, 1, i * 64, 1024, 1, i * 64);
            } else {  // v_c -> fp32 g_V rows c*64+b
                g128(sbase, tid, g_Ahi, g_Alo, g_W3hi, g_W3lo, m0, n0,
                     1024, 1, (i - 1) * 64,
                     g_V, nullptr, nullptr, g_U,
                     64, 1, 0, 1024, 1, i * 64);
            }
            grid_barrier();
        }
    }

    // ---- P3: boundary scan (R7 recurrence structure; warps 0-3 compute) ----
    {
        const int wid = tid >> 5, lane = tid & 31;
        const int nb  = bx & 15, ks = bx >> 4;
        const int n0  = nb * 64;
        const int kb0 = ks * 256;

        // cache E slice once (2048 x 16B chunks over hi+lo)
#pragma unroll
        for (int i = 0; i < 8; i++) {
            int idx = i * 256 + tid;
            int buf = idx >> 10, r = (idx >> 4) & 63, s = idx & 15;
            uint32_t dst = sbase + (buf ? R_EL : R_EH) + (uint32_t)(r * RROW + s * 16);
            const char* src = (const char*)(buf ? g_Nlo : g_Nhi)
                            + (size_t)(n0 + r) * 2048 + kb0 + s * 16;
            cpa16(dst, src);
        }
        cp_commit();
        cp_wait<0>();
        __syncthreads();

        const int j   = lane >> 3;
        const int arl = (lane & 7) + (j & 1) * 8;
        const int brl = (lane & 7) + (j >> 1) * 8;
        float* Pp = g_P + (size_t)ks * (RB * RACT);

        for (int c = 0; c < NCHUNK; c++) {
            if (c > 0) {
                // load s_{c-1} slice from g_Bnd rows c*64
#pragma unroll
                for (int i = 0; i < 8; i++) {
                    int idx = i * 256 + tid;
                    int buf = idx >> 10, r = (idx >> 4) & 63, s = idx & 15;
                    uint32_t dst = sbase + (buf ? R_AL : R_AH) + (uint32_t)(r * RROW + s * 16);
                    const char* src = (const char*)(buf ? g_Bndlo : g_Bndhi)
                                    + (size_t)(c * 64 + r) * 2048 + kb0 + s * 16;
                    cpa16(dst, src);
                }
                cp_commit();
                cp_wait<0>();
                __syncthreads();

                if (wid < 4) {
                    float acc[4][2][4];
#pragma unroll
                    for (int a = 0; a < 4; a++)
#pragma unroll
                        for (int b = 0; b < 2; b++)
#pragma unroll
                            for (int e = 0; e < 4; e++) acc[a][b][e] = 0.f;

#pragma unroll
                    for (int kt = 0; kt < 8; kt++) {
                        const int aseg = kt * 2 + (j >> 1);
                        const int bseg = kt * 2 + (j & 1);
                        uint32_t ah[4][4], al[4][4];
#pragma unroll
                        for (int mt = 0; mt < 4; mt++) {
                            uint32_t ra = sbase + R_AH + (uint32_t)((mt * 16 + arl) * RROW + aseg * 16);
                            ldsm4(ah[mt][0], ah[mt][1], ah[mt][2], ah[mt][3], ra);
                            ldsm4(al[mt][0], al[mt][1], al[mt][2], al[mt][3], ra + (R_AL - R_AH));
                        }
                        uint32_t bh[2][2], bl[2][2];
                        {
                            uint32_t rb = sbase + R_EH + (uint32_t)((wid * 16 + brl) * RROW + bseg * 16);
                            uint32_t t0, t1, t2, t3;
                            ldsm4(t0, t1, t2, t3, rb);
                            bh[0][0] = t0; bh[0][1] = t1; bh[1][0] = t2; bh[1][1] = t3;
                            ldsm4(t0, t1, t2, t3, rb + (R_EL - R_EH));
                            bl[0][0] = t0; bl[0][1] = t1; bl[1][0] = t2; bl[1][1] = t3;
                        }
#pragma unroll
                        for (int mt = 0; mt < 4; mt++)
#pragma unroll
                            for (int nt = 0; nt < 2; nt++) {
                                mma16816(acc[mt][nt], ah[mt], bh[nt]);
                                mma16816(acc[mt][nt], ah[mt], bl[nt]);
                                mma16816(acc[mt][nt], al[mt], bh[nt]);
                            }
                    }

#pragma unroll
                    for (int mt = 0; mt < 4; mt++)
#pragma unroll
                        for (int h = 0; h < 2; h++) {
                            int b = mt * 16 + (lane >> 2) + h * 8;
#pragma unroll
                            for (int nt = 0; nt < 2; nt++) {
                                int icol = n0 + wid * 16 + nt * 8 + (lane & 3) * 2;
                                float2 v;
                                v.x = acc[mt][nt][h * 2];
                                v.y = acc[mt][nt][h * 2 + 1];
                                *reinterpret_cast<float2*>(Pp + (size_t)b * 1024 + icol) = v;
                            }
                        }
                }
            }

            grid_barrier();

            if (tid < 128) {
                const int base = bx * 512 + tid * 4;
                float4 s4 = ldcg4(g_V + (size_t)c * (RB * RACT) + base);
                if (c > 0) {
#pragma unroll
                    for (int p = 0; p < KSPLIT; p++) {
                        float4 v = ldcg4(g_P + (size_t)p * (RB * RACT) + base);
                        s4.x += v.x; s4.y += v.y; s4.z += v.z; s4.w += v.w;
                    }
                }
                ushort4 h4, l4;
                h4.x = f2bh(s4.x); l4.x = f2bl(s4.x, h4.x);
                h4.y = f2bh(s4.y); l4.y = f2bl(s4.y, h4.y);
                h4.z = f2bh(s4.z); l4.z = f2bl(s4.z, h4.z);
                h4.w = f2bh(s4.w); l4.w = f2bl(s4.w, h4.w);
                const size_t doff = (size_t)(c + 1) * (RB * RACT) + base;
                *reinterpret_cast<ushort4*>(g_Bndhi + doff) = h4;
                *reinterpret_cast<ushort4*>(g_Bndlo + doff) = l4;
            }

            grid_barrier();
        }
    }

    // ---- P4: pass2 (exact states) ----
    {
        const int m0 = (bx >> 3) * 128, n0 = (bx & 7) * 128;
        for (int i = 0; i < CHUNK; i++) {
            const __nv_bfloat16* sh = (i == 0) ? g_Bndhi : g_Ahi;
            const __nv_bfloat16* sl = (i == 0) ? g_Bndlo : g_Alo;
            int a0 = (i == 0) ? 64 : 1024;
            int a2 = (i == 0) ? 0 : (i - 1) * 64;
            g128(sbase, tid, sh, sl, g_W3hi, g_W3lo, m0, n0,
                 a0, 1, a2,
                 nullptr, g_Ahi, g_Alo, g_U,
                 1024, 1, i * 64, 1024, 1, i * 64);
            if (i + 1 < CHUNK) grid_barrier();
        }
    }
}

// ---------------- launch: 4 nodes ----------------
extern "C" void kernel_launch(void* const* d_in, const int* in_sizes, int n_in,
                              void* d_out, int out_size)
{
    const float* X   = (const float*)d_in[0];
    const float* Wax = (const float*)d_in[1];
    const float* Waa = (const float*)d_in[2];
    const float* ba  = (const float*)d_in[3];
    const float* Wy  = (const float*)d_in[4];
    const float* by  = (const float*)d_in[5];
    float* out = (float*)d_out;

    cudaFuncSetAttribute(gemm_mma<0>, cudaFuncAttributeMaxDynamicSharedMemorySize, GSMEM);
    cudaFuncSetAttribute(gemm_mma<1>, cudaFuncAttributeMaxDynamicSharedMemorySize, GSMEM);
    cudaFuncSetAttribute(scan_all,    cudaFuncAttributeMaxDynamicSharedMemorySize, GSMEM);

    const int ntot = N4X + 3 * N4W;

    split_all<<<ntot / 256, 256>>>((const float4*)X, (const float4*)Wax,
                                   (const float4*)Wy, (const float4*)Waa);
    gemm_mma<0><<<dim3(8, 256), 256, GSMEM>>>(ba, nullptr);   // U = X @ Wax^T + ba
    scan_all<<<NBLK, 256, GSMEM>>>(Waa);                      // chunked scan -> g_A
    gemm_mma<1><<<dim3(8, 256), 256, GSMEM>>>(by, out);       // out = A @ Wy^T + by
}

// round 9
// speedup vs baseline: 24.4941x; 1.1259x over previous
#include <cuda_runtime.h>
#include <cuda_bf16.h>
#include <cstdint>

#define RB     64
#define RT     512
#define RACT   1024
#define RM     (RT * RB)        // 32768
#define CHUNK  16
#define NCHUNK 32
#define MP     (NCHUNK * RB)    // 2048
#define NBLK   128
#define KSPLIT 8

#define N4X (RM * RACT / 4)
#define N4W (RACT * RACT / 4)

// ---------------- scratch (device globals: allocation-free) ----------------
__device__ __align__(256) float g_U[RM * RACT];
__device__ __align__(256) float g_V[MP * RACT];            // v_c fp32
__device__ __align__(256) float g_P[KSPLIT * RB * RACT];   // boundary partials
__device__ unsigned int g_count;
__device__ volatile unsigned int g_gen;

__device__ __align__(256) __nv_bfloat16 g_Xhi[RM * RACT],  g_Xlo[RM * RACT];
__device__ __align__(256) __nv_bfloat16 g_Ahi[RM * RACT],  g_Alo[RM * RACT];
__device__ __align__(256) __nv_bfloat16 g_W1hi[RACT * RACT], g_W1lo[RACT * RACT]; // Wax
__device__ __align__(256) __nv_bfloat16 g_W2hi[RACT * RACT], g_W2lo[RACT * RACT]; // Wy
__device__ __align__(256) __nv_bfloat16 g_W3hi[RACT * RACT], g_W3lo[RACT * RACT]; // Waa
__device__ __align__(256) __nv_bfloat16 g_Mhi[RACT * RACT],  g_Mlo[RACT * RACT];
__device__ __align__(256) __nv_bfloat16 g_M2hi[RACT * RACT], g_M2lo[RACT * RACT];
__device__ __align__(256) __nv_bfloat16 g_Nhi[RACT * RACT],  g_Nlo[RACT * RACT];
__device__ __align__(256) __nv_bfloat16 g_N2hi[RACT * RACT], g_N2lo[RACT * RACT];
__device__ __align__(256) __nv_bfloat16 g_Bndhi[(NCHUNK + 1) * RB * RACT];
__device__ __align__(256) __nv_bfloat16 g_Bndlo[(NCHUNK + 1) * RB * RACT];

// ---------------- PTX helpers ----------------
__device__ __forceinline__ uint32_t s2u(const void* p) {
    uint32_t a;
    asm("{ .reg .u64 t; cvta.to.shared.u64 t, %1; cvt.u32.u64 %0, t; }" : "=r"(a) : "l"(p));
    return a;
}
__device__ __forceinline__ void cpa16(uint32_t d, const void* s) {
    asm volatile("cp.async.cg.shared.global [%0], [%1], 16;\n" :: "r"(d), "l"(s));
}
__device__ __forceinline__ void cp_commit() { asm volatile("cp.async.commit_group;\n" ::: "memory"); }
template <int N> __device__ __forceinline__ void cp_wait() {
    asm volatile("cp.async.wait_group %0;\n" :: "n"(N) : "memory");
}
__device__ __forceinline__ void ldsm4(uint32_t& r0, uint32_t& r1, uint32_t& r2, uint32_t& r3,
                                      uint32_t addr) {
    asm volatile("ldmatrix.sync.aligned.m8n8.x4.shared.b16 {%0,%1,%2,%3}, [%4];"
                 : "=r"(r0), "=r"(r1), "=r"(r2), "=r"(r3) : "r"(addr));
}
__device__ __forceinline__ void mma16816(float* c, const uint32_t* a, const uint32_t* b) {
    asm volatile(
        "mma.sync.aligned.m16n8k16.row.col.f32.bf16.bf16.f32 "
        "{%0,%1,%2,%3}, {%4,%5,%6,%7}, {%8,%9}, {%0,%1,%2,%3};"
        : "+f"(c[0]), "+f"(c[1]), "+f"(c[2]), "+f"(c[3])
        : "r"(a[0]), "r"(a[1]), "r"(a[2]), "r"(a[3]), "r"(b[0]), "r"(b[1]));
}
__device__ __forceinline__ float4 ldcg4(const float* p) {
    return __ldcg(reinterpret_cast<const float4*>(p));
}

// ---------------- grid barrier (128 blocks, replay-safe) ----------------
__device__ __forceinline__ void grid_barrier() {
    __threadfence();
    __syncthreads();
    if (threadIdx.x == 0) {
        unsigned gen = g_gen;
        unsigned old = atomicAdd(&g_count, 1u);
        if (old == NBLK - 1) {
            g_count = 0;
            __threadfence();
            g_gen = gen + 1;
        } else {
            while (g_gen == gen) { __nanosleep(64); }
        }
    }
    __syncthreads();
    __threadfence();
}

// ---------------- split helpers ----------------
__device__ __forceinline__ unsigned short f2bh(float x) {
    return __bfloat16_as_ushort(__float2bfloat16(x));
}
__device__ __forceinline__ unsigned short f2bl(float x, unsigned short h) {
    return __bfloat16_as_ushort(__float2bfloat16(x - __bfloat162float(__ushort_as_bfloat16(h))));
}

__global__ void split_all(const float4* __restrict__ X,
                          const float4* __restrict__ W1,
                          const float4* __restrict__ W2,
                          const float4* __restrict__ W3)
{
    int i = blockIdx.x * blockDim.x + threadIdx.x;
    const float4* src;
    ushort4 *hi, *lo;
    int off;
    if (i < N4X) {
        src = X; off = i;
        hi = (ushort4*)g_Xhi; lo = (ushort4*)g_Xlo;
    } else {
        int j = i - N4X;
        int w = j / N4W;
        off   = j - w * N4W;
        if (w == 0)      { src = W1; hi = (ushort4*)g_W1hi; lo = (ushort4*)g_W1lo; }
        else if (w == 1) { src = W2; hi = (ushort4*)g_W2hi; lo = (ushort4*)g_W2lo; }
        else             { src = W3; hi = (ushort4*)g_W3hi; lo = (ushort4*)g_W3lo; }
    }
    float4 v = src[off];
    ushort4 h, l;
    h.x = f2bh(v.x); l.x = f2bl(v.x, h.x);
    h.y = f2bh(v.y); l.y = f2bl(v.y, h.y);
    h.z = f2bh(v.z); l.z = f2bl(v.z, h.z);
    h.w = f2bh(v.w); l.w = f2bl(v.w, h.w);
    hi[off] = h; lo[off] = l;
}

// ---------------- device-function 128x128 GEMM tile, KC=64 stages ----------------
// C[m][n] = sum_k A[m][k]*B[n][k] (bf16x3). A-row remap (a0,a1,a2); B rows plain n0+r.
// Cf != null -> fp32 store (+bias if non-null, +Uf if non-null); else bf16 split (+Uf).
#define KC      64
#define RBYTES  144                 // 128B data + 16B pad (36-bank stride: conflict-free)
#define TILE_B  (128 * RBYTES)      // 18432
#define STG_B   (4 * TILE_B)        // 73728 (Ah, Al, Bh, Bl)
#define NCH     (1024 / KC)         // 16 chunks
#define GSMEM   (2 * STG_B)         // 147456, 2-stage pipe

__device__ void g128(uint32_t sbase, int tid,
    const __nv_bfloat16* Ah, const __nv_bfloat16* Al,
    const __nv_bfloat16* Bh, const __nv_bfloat16* Bl,
    int m0, int n0, int a0, int a1, int a2,
    const float* bias,
    float* Cf, __nv_bfloat16* Chi, __nv_bfloat16* Clo,
    const float* Uf,
    int c0, int c1, int c2, int u0, int u1, int u2)
{
    const int wid = tid >> 5, lane = tid & 31;
    const int wM  = (wid & 1) * 64;
    const int wN  = (wid >> 1) * 32;

    // loader mapping: thread covers rows rA + j*32 (j=0..3) in each of 4 buffers, seg s16
    const int rA  = tid >> 3;              // 0..31
    const int s16 = (tid & 7) * 16;
    size_t offM[4], offN[4];
#pragma unroll
    for (int j = 0; j < 4; j++) {
        int rm = m0 + rA + j * 32;
        offM[j] = (size_t)((rm >> 6) * a0 + (rm & 63) * a1 + a2) * 2048;
        offN[j] = (size_t)(n0 + rA + j * 32) * 2048;
    }
    const uint32_t dbase = (uint32_t)(rA * RBYTES + s16);

    // prologue: stage 0 <- chunk 0
    {
        uint32_t ss = sbase;
#pragma unroll
        for (int j = 0; j < 4; j++) {
            uint32_t d = ss + (uint32_t)(j * 32 * RBYTES) + dbase;
            cpa16(d,              (const char*)Ah + offM[j] + s16);
            cpa16(d + TILE_B,     (const char*)Al + offM[j] + s16);
            cpa16(d + 2 * TILE_B, (const char*)Bh + offN[j] + s16);
            cpa16(d + 3 * TILE_B, (const char*)Bl + offN[j] + s16);
        }
        cp_commit();
    }

    float acc[4][4][4];
#pragma unroll
    for (int a = 0; a < 4; a++)
#pragma unroll
        for (int b = 0; b < 4; b++)
#pragma unroll
            for (int c = 0; c < 4; c++) acc[a][b][c] = 0.f;

    const int j4  = lane >> 3;
    const int arl = (lane & 7) + (j4 & 1) * 8;
    const int brl = (lane & 7) + (j4 >> 1) * 8;

    for (int c = 0; c < NCH; c++) {
        cp_wait<0>();            // chunk c data complete (this thread's groups)
        __syncthreads();         // visible to all; all warps done reading buffer (c+1)&1
        if (c + 1 < NCH) {       // prefetch chunk c+1 into the other buffer
            uint32_t ss = sbase + (uint32_t)((c + 1) & 1) * STG_B;
            int co = (c + 1) * (KC * 2);
#pragma unroll
            for (int j = 0; j < 4; j++) {
                uint32_t d = ss + (uint32_t)(j * 32 * RBYTES) + dbase;
                cpa16(d,              (const char*)Ah + offM[j] + co + s16);
                cpa16(d + TILE_B,     (const char*)Al + offM[j] + co + s16);
                cpa16(d + 2 * TILE_B, (const char*)Bh + offN[j] + co + s16);
                cpa16(d + 3 * TILE_B, (const char*)Bl + offN[j] + co + s16);
            }
            cp_commit();
        }

        const uint32_t ss = sbase + (uint32_t)(c & 1) * STG_B;
#pragma unroll
        for (int kt = 0; kt < 4; kt++) {
            const int aseg = kt * 2 + (j4 >> 1);
            const int bseg = kt * 2 + (j4 & 1);
            uint32_t ah[4][4], al[4][4];
#pragma unroll
            for (int mt = 0; mt < 4; mt++) {
                uint32_t ra = ss + (uint32_t)((wM + mt * 16 + arl) * RBYTES + aseg * 16);
                ldsm4(ah[mt][0], ah[mt][1], ah[mt][2], ah[mt][3], ra);
                ldsm4(al[mt][0], al[mt][1], al[mt][2], al[mt][3], ra + TILE_B);
            }
            uint32_t bh[4][2], bl[4][2];
#pragma unroll
            for (int bt = 0; bt < 2; bt++) {
                uint32_t rb = ss + 2 * TILE_B
                            + (uint32_t)((wN + bt * 16 + brl) * RBYTES + bseg * 16);
                uint32_t t0, t1, t2, t3;
                ldsm4(t0, t1, t2, t3, rb);
                bh[bt * 2][0] = t0; bh[bt * 2][1] = t1;
                bh[bt * 2 + 1][0] = t2; bh[bt * 2 + 1][1] = t3;
                ldsm4(t0, t1, t2, t3, rb + TILE_B);
                bl[bt * 2][0] = t0; bl[bt * 2][1] = t1;
                bl[bt * 2 + 1][0] = t2; bl[bt * 2 + 1][1] = t3;
            }
#pragma unroll
            for (int mt = 0; mt < 4; mt++)
#pragma unroll
                for (int nt = 0; nt < 4; nt++) {
                    mma16816(acc[mt][nt], ah[mt], bh[nt]);
                    mma16816(acc[mt][nt], ah[mt], bl[nt]);
                    mma16816(acc[mt][nt], al[mt], bh[nt]);
                }
        }
    }

#pragma unroll
    for (int mt = 0; mt < 4; mt++)
#pragma unroll
        for (int h = 0; h < 2; h++) {
            int row = m0 + wM + mt * 16 + (lane >> 2) + h * 8;
            size_t crow = (size_t)((row >> 6) * c0 + (row & 63) * c1 + c2);
            size_t urow = (size_t)((row >> 6) * u0 + (row & 63) * u1 + u2);
#pragma unroll
            for (int nt = 0; nt < 4; nt++) {
                int col = n0 + wN + nt * 8 + (lane & 3) * 2;
                float vx = acc[mt][nt][h * 2];
                float vy = acc[mt][nt][h * 2 + 1];
                if (Uf) {
                    float2 u = *reinterpret_cast<const float2*>(Uf + urow * 1024 + col);
                    vx += u.x; vy += u.y;
                }
                if (Cf) {
                    if (bias) { vx += bias[col]; vy += bias[col + 1]; }
                    float2 v; v.x = vx; v.y = vy;
                    *reinterpret_cast<float2*>(Cf + crow * 1024 + col) = v;
                } else {
                    unsigned short hx = f2bh(vx), lx = f2bl(vx, hx);
                    unsigned short hy = f2bh(vy), ly = f2bl(vy, hy);
                    ushort2 hv = {hx, hy}, lv = {lx, ly};
                    *reinterpret_cast<ushort2*>(Chi + crow * 1024 + col) = hv;
                    *reinterpret_cast<ushort2*>(Clo + crow * 1024 + col) = lv;
                }
            }
        }
}

// ---------------- standalone GEMM wrappers ----------------
template <int MODE>
__global__ void __launch_bounds__(256, 1) gemm_mma(const float* __restrict__ bias,
                                                   float* __restrict__ Cext)
{
    extern __shared__ char smc[];
    const int n0 = blockIdx.x * 128, m0 = blockIdx.y * 128;
    if (MODE == 0) {
        g128(s2u(smc), threadIdx.x, g_Xhi, g_Xlo, g_W1hi, g_W1lo, m0, n0,
             1, 512, 0, bias, g_U, nullptr, nullptr, nullptr,
             64, 1, 0, 0, 0, 0);
    } else {
        g128(s2u(smc), threadIdx.x, g_Ahi, g_Alo, g_W2hi, g_W2lo, m0, n0,
             64, 1, 0, bias, Cext, nullptr, nullptr, nullptr,
             1, 512, 0, 0, 0, 0);
    }
}

// ---------------- persistent scan kernel ----------------
#define RROW 272
#define R_AH 0
#define R_AL (64 * RROW)
#define R_EH (2 * 64 * RROW)
#define R_EL (3 * 64 * RROW)

__global__ void __launch_bounds__(256, 1) scan_all(const float* __restrict__ Waa)
{
    extern __shared__ char smc[];
    const uint32_t sbase = s2u(smc);
    const int tid = threadIdx.x;
    const int bx  = blockIdx.x;
    const int gt  = bx * 256 + tid;

    // ---- P0: W^T split, chunk-head split, zero Bnd ----
    for (int g = gt; g < 1024 * 1024; g += 32768) {
        int jr = g >> 10, ir = g & 1023;
        float v = Waa[(size_t)ir * 1024 + jr];
        unsigned short h = f2bh(v), l = f2bl(v, h);
        g_Mhi[g] = __ushort_as_bfloat16(h);
        g_Mlo[g] = __ushort_as_bfloat16(l);
    }
    for (int g = gt; g < MP * 256; g += 32768) {
        int row = g >> 8, c4 = (g & 255) * 4;
        size_t off = ((size_t)((row >> 6) * 1024 + (row & 63))) * 1024 + c4;
        float4 v = *reinterpret_cast<const float4*>(g_U + off);
        ushort4 h, l;
        h.x = f2bh(v.x); l.x = f2bl(v.x, h.x);
        h.y = f2bh(v.y); l.y = f2bl(v.y, h.y);
        h.z = f2bh(v.z); l.z = f2bl(v.z, h.z);
        h.w = f2bh(v.w); l.w = f2bl(v.w, h.w);
        *reinterpret_cast<ushort4*>(g_Ahi + off) = h;
        *reinterpret_cast<ushort4*>(g_Alo + off) = l;
    }
    {
        ushort4 z = {0, 0, 0, 0};
        for (int g = gt; g < 16384; g += 32768) {
            reinterpret_cast<ushort4*>(g_Bndhi)[g] = z;
            reinterpret_cast<ushort4*>(g_Bndlo)[g] = z;
        }
    }
    grid_barrier();

    // ---- P1: E = W^16 (4 dual-orientation squarings) ----
    {
        const __nv_bfloat16 *rMh[4] = {g_Mhi,  g_M2hi, g_Mhi,  g_M2hi};
        const __nv_bfloat16 *rMl[4] = {g_Mlo,  g_M2lo, g_Mlo,  g_M2lo};
        const __nv_bfloat16 *rNh[4] = {g_W3hi, g_N2hi, g_Nhi,  g_N2hi};
        const __nv_bfloat16 *rNl[4] = {g_W3lo, g_N2lo, g_Nlo,  g_N2lo};
        __nv_bfloat16 *wMh[4] = {g_M2hi, g_Mhi, g_M2hi, g_Mhi};
        __nv_bfloat16 *wMl[4] = {g_M2lo, g_Mlo, g_M2lo, g_Mlo};
        __nv_bfloat16 *wNh[4] = {g_N2hi, g_Nhi, g_N2hi, g_Nhi};
        __nv_bfloat16 *wNl[4] = {g_N2lo, g_Nlo, g_N2lo, g_Nlo};

        const int o  = bx >> 6;
        const int t6 = bx & 63;
        const int m0 = (t6 >> 3) * 128, n0 = (t6 & 7) * 128;
        for (int L = 0; L < 4; L++) {
            const __nv_bfloat16 *Ah = o ? rNh[L] : rMh[L], *Al = o ? rNl[L] : rMl[L];
            const __nv_bfloat16 *Bh = o ? rMh[L] : rNh[L], *Bl = o ? rMl[L] : rNl[L];
            __nv_bfloat16 *Ch = o ? wNh[L] : wMh[L], *Cl = o ? wNl[L] : wMl[L];
            g128(sbase, tid, Ah, Al, Bh, Bl, m0, n0, 64, 1, 0,
                 nullptr, nullptr, Ch, Cl, nullptr, 64, 1, 0, 0, 0, 0);
            grid_barrier();
        }
    }

    // ---- P2: pass1 (local recurrence, zero init) ----
    {
        const int m0 = (bx >> 3) * 128, n0 = (bx & 7) * 128;
        for (int i = 1; i < CHUNK; i++) {
            if (i < CHUNK - 1) {
                g128(sbase, tid, g_Ahi, g_Alo, g_W3hi, g_W3lo, m0, n0,
                     1024, 1, (i - 1) * 64, nullptr,
                     nullptr, g_Ahi, g_Alo, g_U,
                     1024, 1, i * 64, 1024, 1, i * 64);
            } else {
                g128(sbase, tid, g_Ahi, g_Alo, g_W3hi, g_W3lo, m0, n0,
                     1024, 1, (i - 1) * 64, nullptr,
                     g_V, nullptr, nullptr, g_U,
                     64, 1, 0, 1024, 1, i * 64);
            }
            grid_barrier();
        }
    }

    // ---- P3: boundary scan (32 steps; verbatim R8 structure) ----
    {
        const int wid = tid >> 5, lane = tid & 31;
        const int nb  = bx & 15, ks = bx >> 4;
        const int n0  = nb * 64;
        const int kb0 = ks * 256;

#pragma unroll
        for (int i = 0; i < 8; i++) {
            int idx = i * 256 + tid;
            int buf = idx >> 10, r = (idx >> 4) & 63, s = idx & 15;
            uint32_t dst = sbase + (buf ? R_EL : R_EH) + (uint32_t)(r * RROW + s * 16);
            const char* src = (const char*)(buf ? g_Nlo : g_Nhi)
                            + (size_t)(n0 + r) * 2048 + kb0 + s * 16;
            cpa16(dst, src);
        }
        cp_commit();
        cp_wait<0>();
        __syncthreads();

        const int j   = lane >> 3;
        const int arl = (lane & 7) + (j & 1) * 8;
        const int brl = (lane & 7) + (j >> 1) * 8;
        float* Pp = g_P + (size_t)ks * (RB * RACT);

        for (int c = 0; c < NCHUNK; c++) {
            if (c > 0) {
#pragma unroll
                for (int i = 0; i < 8; i++) {
                    int idx = i * 256 + tid;
                    int buf = idx >> 10, r = (idx >> 4) & 63, s = idx & 15;
                    uint32_t dst = sbase + (buf ? R_AL : R_AH) + (uint32_t)(r * RROW + s * 16);
                    const char* src = (const char*)(buf ? g_Bndlo : g_Bndhi)
                                    + (size_t)(c * 64 + r) * 2048 + kb0 + s * 16;
                    cpa16(dst, src);
                }
                cp_commit();
                cp_wait<0>();
                __syncthreads();

                if (wid < 4) {
                    float acc[4][2][4];
#pragma unroll
                    for (int a = 0; a < 4; a++)
#pragma unroll
                        for (int b = 0; b < 2; b++)
#pragma unroll
                            for (int e = 0; e < 4; e++) acc[a][b][e] = 0.f;

#pragma unroll
                    for (int kt = 0; kt < 8; kt++) {
                        const int aseg = kt * 2 + (j >> 1);
                        const int bseg = kt * 2 + (j & 1);
                        uint32_t ah[4][4], al[4][4];
#pragma unroll
                        for (int mt = 0; mt < 4; mt++) {
                            uint32_t ra = sbase + R_AH + (uint32_t)((mt * 16 + arl) * RROW + aseg * 16);
                            ldsm4(ah[mt][0], ah[mt][1], ah[mt][2], ah[mt][3], ra);
                            ldsm4(al[mt][0], al[mt][1], al[mt][2], al[mt][3], ra + (R_AL - R_AH));
                        }
                        uint32_t bh[2][2], bl[2][2];
                        {
                            uint32_t rb = sbase + R_EH + (uint32_t)((wid * 16 + brl) * RROW + bseg * 16);
                            uint32_t t0, t1, t2, t3;
                            ldsm4(t0, t1, t2, t3, rb);
                            bh[0][0] = t0; bh[0][1] = t1; bh[1][0] = t2; bh[1][1] = t3;
                            ldsm4(t0, t1, t2, t3, rb + (R_EL - R_EH));
                            bl[0][0] = t0; bl[0][1] = t1; bl[1][0] = t2; bl[1][1] = t3;
                        }
#pragma unroll
                        for (int mt = 0; mt < 4; mt++)
#pragma unroll
                            for (int nt = 0; nt < 2; nt++) {
                                mma16816(acc[mt][nt], ah[mt], bh[nt]);
                                mma16816(acc[mt][nt], ah[mt], bl[nt]);
                                mma16816(acc[mt][nt], al[mt], bh[nt]);
                            }
                    }

#pragma unroll
                    for (int mt = 0; mt < 4; mt++)
#pragma unroll
                        for (int h = 0; h < 2; h++) {
                            int b = mt * 16 + (lane >> 2) + h * 8;
#pragma unroll
                            for (int nt = 0; nt < 2; nt++) {
                                int icol = n0 + wid * 16 + nt * 8 + (lane & 3) * 2;
                                float2 v;
                                v.x = acc[mt][nt][h * 2];
                                v.y = acc[mt][nt][h * 2 + 1];
                                *reinterpret_cast<float2*>(Pp + (size_t)b * 1024 + icol) = v;
                            }
                        }
                }
            }

            grid_barrier();

            if (tid < 128) {
                const int base = bx * 512 + tid * 4;
                float4 s4 = ldcg4(g_V + (size_t)c * (RB * RACT) + base);
                if (c > 0) {
#pragma unroll
                    for (int p = 0; p < KSPLIT; p++) {
                        float4 v = ldcg4(g_P + (size_t)p * (RB * RACT) + base);
                        s4.x += v.x; s4.y += v.y; s4.z += v.z; s4.w += v.w;
                    }
                }
                ushort4 h4, l4;
                h4.x = f2bh(s4.x); l4.x = f2bl(s4.x, h4.x);
                h4.y = f2bh(s4.y); l4.y = f2bl(s4.y, h4.y);
                h4.z = f2bh(s4.z); l4.z = f2bl(s4.z, h4.z);
                h4.w = f2bh(s4.w); l4.w = f2bl(s4.w, h4.w);
                const size_t doff = (size_t)(c + 1) * (RB * RACT) + base;
                *reinterpret_cast<ushort4*>(g_Bndhi + doff) = h4;
                *reinterpret_cast<ushort4*>(g_Bndlo + doff) = l4;
            }

            grid_barrier();
        }
    }

    // ---- P4: pass2 (exact states) ----
    {
        const int m0 = (bx >> 3) * 128, n0 = (bx & 7) * 128;
        for (int i = 0; i < CHUNK; i++) {
            const __nv_bfloat16* sh = (i == 0) ? g_Bndhi : g_Ahi;
            const __nv_bfloat16* sl = (i == 0) ? g_Bndlo : g_Alo;
            int a0 = (i == 0) ? 64 : 1024;
            int a2 = (i == 0) ? 0 : (i - 1) * 64;
            g128(sbase, tid, sh, sl, g_W3hi, g_W3lo, m0, n0,
                 a0, 1, a2, nullptr,
                 nullptr, g_Ahi, g_Alo, g_U,
                 1024, 1, i * 64, 1024, 1, i * 64);
            if (i + 1 < CHUNK) grid_barrier();
        }
    }
}

// ---------------- launch: 4 nodes ----------------
extern "C" void kernel_launch(void* const* d_in, const int* in_sizes, int n_in,
                              void* d_out, int out_size)
{
    const float* X   = (const float*)d_in[0];
    const float* Wax = (const float*)d_in[1];
    const float* Waa = (const float*)d_in[2];
    const float* ba  = (const float*)d_in[3];
    const float* Wy  = (const float*)d_in[4];
    const float* by  = (const float*)d_in[5];
    float* out = (float*)d_out;

    cudaFuncSetAttribute(gemm_mma<0>, cudaFuncAttributeMaxDynamicSharedMemorySize, GSMEM);
    cudaFuncSetAttribute(gemm_mma<1>, cudaFuncAttributeMaxDynamicSharedMemorySize, GSMEM);
    cudaFuncSetAttribute(scan_all,    cudaFuncAttributeMaxDynamicSharedMemorySize, GSMEM);

    const int ntot = N4X + 3 * N4W;

    split_all<<<ntot / 256, 256>>>((const float4*)X, (const float4*)Wax,
                                   (const float4*)Wy, (const float4*)Waa);
    gemm_mma<0><<<dim3(8, 256), 256, GSMEM>>>(ba, nullptr);   // U = X @ Wax^T + ba
    scan_all<<<NBLK, 256, GSMEM>>>(Waa);                      // chunked scan -> g_A
    gemm_mma<1><<<dim3(8, 256), 256, GSMEM>>>(by, out);       // out = A @ Wy^T + by
}